// round 10
// baseline (speedup 1.0000x reference)
#include <cuda_runtime.h>
#include <math.h>

#define ND   768
#define NB   8
#define NCH  3
#define NMIX 5
#define NS   10
#define HH   10
#define PI2f 6.28318530717958647692f
#define ZITTERf 1e-4f
#define NPLANE (NB*NCH*NMIX)          // 120
#define LOG2Ef 1.4426950408889634f

__device__ float    g_feat[NPLANE * ND];   // zero-init; kA atomics; k34 reads then re-zeroes
__device__ float    g_hmean[NB * NCH * HH];
__device__ float    g_w[NB * NCH * NMIX];
__device__ unsigned g_ctr;                 // zero-init; k34 last-block counter (self-resetting)

__device__ __forceinline__ float ex2(float x) {
    float y; asm("ex2.approx.ftz.f32 %0, %1;" : "=f"(y) : "f"(x)); return y;
}

// ---------------------------------------------------------------------------
// Kernel A: feature[bc,m,i] = sum_j K_m(i,j)*yc[j], trig-separated.
// Tile: 64 i x 256 j. Thread: i = t>>2, jq = t&3 over 64 consecutive j.
// (unchanged from R7 best)
// ---------------------------------------------------------------------------
#define JPA 280    // padded table stride for 256 j

__global__ void __launch_bounds__(256) kA_feat(const float* __restrict__ xc,
                                               const float* __restrict__ yc,
                                               const float* __restrict__ mu,
                                               const float* __restrict__ inv_std)
{
    int bc  = blockIdx.z;                 // b*3 + c
    int b   = bc / NCH, c = bc - b*NCH;
    int it  = blockIdx.y;
    int jt0 = blockIdx.x * 256;
    int t   = threadIdx.x;

    __shared__ float sC[NMIX*JPA], sS[NMIX*JPA], sXj[JPA];

    float Bv[NMIX], Pv[NMIX];
    #pragma unroll
    for (int m = 0; m < NMIX; m++) {
        float s = inv_std[m];
        Bv[m] = -0.5f * PI2f * PI2f * LOG2Ef * s * s;
        Pv[m] = PI2f * mu[m];
    }

    {   // table setup: every thread owns one j
        int j  = t;
        int gj = jt0 + j;
        float xjv = xc[(b*ND + gj)*NCH + c];
        float yjv = yc[(b*ND + gj)*NCH + c];
        int pj = j + ((j >> 6) << 3);
        sXj[pj] = xjv;
        #pragma unroll
        for (int m = 0; m < NMIX; m++) {
            float sn, cs;
            __sincosf(Pv[m] * xjv, &sn, &cs);
            sC[m*JPA + pj] = cs * yjv;
            sS[m*JPA + pj] = sn * yjv;
        }
    }
    __syncthreads();

    int i_loc = t >> 2, jq = t & 3;
    int gi = it*64 + i_loc;
    float xi = xc[(b*ND + gi)*NCH + c];

    float cI[NMIX], sI[NMIX];
    #pragma unroll
    for (int m = 0; m < NMIX; m++)
        __sincosf(Pv[m] * xi, &sI[m], &cI[m]);

    float accC[NMIX], accS[NMIX];
    #pragma unroll
    for (int m = 0; m < NMIX; m++) { accC[m] = 0.f; accS[m] = 0.f; }

    int gbase = jq * 72;
    #pragma unroll 4
    for (int ch = 0; ch < 16; ch++) {
        int off = gbase + ch*4;
        float4 xv = *reinterpret_cast<const float4*>(&sXj[off]);
        float d0 = xi - xv.x, d1 = xi - xv.y, d2 = xi - xv.z, d3 = xi - xv.w;
        float e0 = d0*d0, e1 = d1*d1, e2 = d2*d2, e3 = d3*d3;
        #pragma unroll
        for (int m = 0; m < NMIX; m++) {
            float Bm = Bv[m];
            float4 cj = *reinterpret_cast<const float4*>(&sC[m*JPA + off]);
            float4 sj = *reinterpret_cast<const float4*>(&sS[m*JPA + off]);
            float v0 = ex2(Bm*e0), v1 = ex2(Bm*e1), v2 = ex2(Bm*e2), v3 = ex2(Bm*e3);
            accC[m] += v0*cj.x + v1*cj.y + v2*cj.z + v3*cj.w;
            accS[m] += v0*sj.x + v1*sj.y + v2*sj.z + v3*sj.w;
        }
    }

    #pragma unroll
    for (int m = 0; m < NMIX; m++) {
        accC[m] += __shfl_xor_sync(0xffffffffu, accC[m], 1);
        accC[m] += __shfl_xor_sync(0xffffffffu, accC[m], 2);
        accS[m] += __shfl_xor_sync(0xffffffffu, accS[m], 1);
        accS[m] += __shfl_xor_sync(0xffffffffu, accS[m], 2);
    }
    if (jq == 0) {
        #pragma unroll
        for (int m = 0; m < NMIX; m++)
            atomicAdd(&g_feat[(bc*NMIX + m)*ND + gi],
                      cI[m]*accC[m] + sI[m]*accS[m]);
    }
}

// ---------------------------------------------------------------------------
// Kernel 34: per-bc hmean (+ re-zero g_feat), then last block runs the MLP
// + Gumbel-softmax. (unchanged)
// ---------------------------------------------------------------------------
__global__ void __launch_bounds__(256) k34_hmean_mlp(
        const float* __restrict__ yc,
        const float* __restrict__ W1, const float* __restrict__ b1,
        const float* __restrict__ W2, const float* __restrict__ b2,
        const float* __restrict__ W3, const float* __restrict__ b3,
        const float* __restrict__ W4, const float* __restrict__ b4,
        const float* __restrict__ W5, const float* __restrict__ b5,
        const float* __restrict__ unif)
{
    int bc = blockIdx.x;
    int b  = bc / NCH, c = bc - b*NCH;
    int t  = threadIdx.x;

    __shared__ float sW[HH*6], sb[HH], sh[HH];
    __shared__ float w2[300], w3[100], w4[100], w5[150];
    __shared__ float sb2[HH], sb3[HH], sb4[HH], sb5[15];
    __shared__ float su[NB*NS*NCH*NMIX];          // 1200 floats
    __shared__ float shm[NB][30], haL[NB][HH], hbL[NB][HH], ll[NB][15], swacc[NB][15];
    __shared__ bool  isLast;

    for (int u = t; u < 300; u += 256) w2[u] = W2[u];
    for (int u = t; u < 1200; u += 256) su[u] = unif[u];
    if (t < 100) { w3[t] = W3[t]; w4[t] = W4[t]; }
    if (t < 150) w5[t] = W5[t];
    if (t < HH)  { sb2[t] = b2[t]; sb3[t] = b3[t]; sb4[t] = b4[t]; }
    if (t < 15)  sb5[t] = b5[t];
    if (t < HH*6) sW[t] = W1[t];
    if (t < HH)  { sb[t] = b1[t]; sh[t] = 0.f; }
    __syncthreads();

    float hacc[HH];
    #pragma unroll
    for (int k = 0; k < HH; k++) hacc[k] = 0.f;

    for (int i = t; i < ND; i += 256) {
        float ycv = yc[(b*ND + i)*NCH + c];
        float f[6];
        #pragma unroll
        for (int m = 0; m < NMIX; m++) {
            int idx = (bc*NMIX + m)*ND + i;
            f[m] = g_feat[idx] + ZITTERf * ycv;
            g_feat[idx] = 0.f;                    // restore invariant for next replay
        }
        f[5] = ycv;
        #pragma unroll
        for (int k = 0; k < HH; k++) {
            float s = sb[k];
            #pragma unroll
            for (int u = 0; u < 6; u++) s += sW[k*6 + u] * f[u];
            hacc[k] += fmaxf(s, 0.f);
        }
    }
    #pragma unroll
    for (int k = 0; k < HH; k++) atomicAdd(&sh[k], hacc[k]);
    __syncthreads();
    if (t < HH)
        g_hmean[b*(NCH*HH) + c*HH + t] = sh[t] * (1.0f/ND);

    __threadfence();
    __syncthreads();
    if (t == 0) isLast = (atomicAdd(&g_ctr, 1u) == (unsigned)(NB*NCH - 1));
    __syncthreads();
    if (!isLast) return;
    if (t == 0) g_ctr = 0;

    if (t < NB*30) {
        const volatile float* hmv = g_hmean;
        shm[t/30][t%30] = hmv[t];
    }
    if (t < NB*15) swacc[t/15][t%15] = 0.f;
    __syncthreads();

    if (t < NB*HH) {
        int bb = t/HH, k = t%HH;
        float s = sb2[k];
        #pragma unroll
        for (int u = 0; u < 30; u++) s += w2[k*30+u] * shm[bb][u];
        haL[bb][k] = fmaxf(s, 0.f);
    }
    __syncthreads();
    if (t < NB*HH) {
        int bb = t/HH, k = t%HH;
        float s = sb3[k];
        #pragma unroll
        for (int u = 0; u < HH; u++) s += w3[k*HH+u] * haL[bb][u];
        hbL[bb][k] = fmaxf(s, 0.f);
    }
    __syncthreads();
    if (t < NB*HH) {
        int bb = t/HH, k = t%HH;
        float s = sb4[k];
        #pragma unroll
        for (int u = 0; u < HH; u++) s += w4[k*HH+u] * hbL[bb][u];
        haL[bb][k] = fmaxf(s, 0.f);
    }
    __syncthreads();
    if (t < NB*15) {
        int bb = t/15, n = t%15;
        float s = sb5[n];
        #pragma unroll
        for (int k = 0; k < HH; k++) s += w5[n*HH+k] * haL[bb][k];
        ll[bb][n] = s;
    }
    __syncthreads();

    if (t < NB*NS*NCH) {
        int bb = t / (NS*NCH);
        int rem = t % (NS*NCH);
        int s_ = rem / NCH, cc = rem % NCH;
        float z[NMIX], mx = -1e30f;
        #pragma unroll
        for (int m = 0; m < NMIX; m++) {
            float u = su[((bb*NS + s_)*NCH + cc)*NMIX + m];
            float g = -__logf(-__logf(u + 1e-20f));
            z[m] = (g + ll[bb][cc*NMIX + m]) * 10.0f;   // 1/TEMP
            mx = fmaxf(mx, z[m]);
        }
        float sum = 0.f;
        #pragma unroll
        for (int m = 0; m < NMIX; m++) { z[m] = __expf(z[m] - mx); sum += z[m]; }
        float inv = 1.0f / (sum * (float)NS);
        #pragma unroll
        for (int m = 0; m < NMIX; m++)
            atomicAdd(&swacc[bb][cc*NMIX + m], z[m] * inv);
    }
    __syncthreads();
    if (t < NB*NCH*NMIX)
        g_w[t] = swacc[t/(NCH*NMIX)][t%(NCH*NMIX)];
}

// ---------------------------------------------------------------------------
// Kernel B (v3): out[b,i,j,c] = sum_m w*K + diag. Trig-separated, full grid.
// Tile 32 i x 256 j; 8 warps, each warp does 4 rows as 2 row-pairs.
// LANE-CONSECUTIVE j chunks: lane l owns j = l*4 (A) and 128 + l*4 (B), so
// warp stores are contiguous (3x wavefront inflation only, ~5us total).
// Tables read once per row-PAIR (LDS halved vs 1-row). ~100 regs, no cap.
// ---------------------------------------------------------------------------
#define KB_IT 32
#define KB_JT 256

__global__ void __launch_bounds__(256) kB_out(float* __restrict__ out,
                                              const float* __restrict__ xc,
                                              const float* __restrict__ mu,
                                              const float* __restrict__ inv_std,
                                              const float* __restrict__ likerr)
{
    int b   = blockIdx.z;
    int it0 = blockIdx.y * KB_IT;
    int jt0 = blockIdx.x * KB_JT;
    int t   = threadIdx.x;

    __shared__ float sC[NCH*NMIX*KB_JT];   // (cos(P*xj) * w)  [c*5+m][j]
    __shared__ float sS[NCH*NMIX*KB_JT];   // (sin(P*xj) * w)
    __shared__ float sXj[NCH*KB_JT];
    __shared__ float sFI[KB_IT*30];        // [row][(c*5+m)*2 + {cos,sin}]
    __shared__ float sXi[KB_IT*NCH];

    float Bv[NMIX], Pv[NMIX];
    #pragma unroll
    for (int m = 0; m < NMIX; m++) {
        float s = inv_std[m];
        Bv[m] = -0.5f * PI2f * PI2f * LOG2Ef * s * s;
        Pv[m] = PI2f * mu[m];
    }
    float sd[NCH];
    #pragma unroll
    for (int c = 0; c < NCH; c++) {
        float l = fminf(fmaxf(likerr[c], 0.1f), 1.0f);
        sd[c] = ZITTERf + l*l;
    }

    {   // j tables: one j per thread
        int j = t;
        #pragma unroll
        for (int c = 0; c < NCH; c++) {
            float xjv = xc[(b*ND + jt0 + j)*NCH + c];
            sXj[c*KB_JT + j] = xjv;
            #pragma unroll
            for (int m = 0; m < NMIX; m++) {
                float sn, cs;
                __sincosf(Pv[m] * xjv, &sn, &cs);
                float wv = g_w[(b*NCH + c)*NMIX + m];
                sC[(c*NMIX + m)*KB_JT + j] = cs * wv;
                sS[(c*NMIX + m)*KB_JT + j] = sn * wv;
            }
        }
    }
    // i tables
    for (int u = t; u < KB_IT*15; u += 256) {
        int row = u / 15, cm = u % 15, c = cm / 5, m = cm % 5;
        float xiv = xc[(b*ND + it0 + row)*NCH + c];
        float sn, cs;
        __sincosf(Pv[m] * xiv, &sn, &cs);
        sFI[row*30 + cm*2    ] = cs;
        sFI[row*30 + cm*2 + 1] = sn;
        if (m == 0) sXi[row*NCH + c] = xiv;
    }
    __syncthreads();

    int w = t >> 5, l = t & 31;
    int jA = l*4, jB = 128 + l*4;

    #pragma unroll
    for (int rp = 0; rp < 2; rp++) {
        int r0  = w*4 + rp*2;
        int gi0 = it0 + r0, gi1 = gi0 + 1;

        float o0A[12], o0B[12], o1A[12], o1B[12];
        #pragma unroll
        for (int u = 0; u < 12; u++) { o0A[u]=0.f; o0B[u]=0.f; o1A[u]=0.f; o1B[u]=0.f; }

        #pragma unroll
        for (int c = 0; c < NCH; c++) {
            float4 xvA = *reinterpret_cast<const float4*>(&sXj[c*KB_JT + jA]);
            float4 xvB = *reinterpret_cast<const float4*>(&sXj[c*KB_JT + jB]);
            float xi0 = sXi[r0*NCH + c], xi1 = sXi[(r0+1)*NCH + c];

            float e0A[4], e0B[4], e1A[4], e1B[4];
            {
                float d;
                d = xi0-xvA.x; e0A[0]=d*d;  d = xi0-xvA.y; e0A[1]=d*d;
                d = xi0-xvA.z; e0A[2]=d*d;  d = xi0-xvA.w; e0A[3]=d*d;
                d = xi0-xvB.x; e0B[0]=d*d;  d = xi0-xvB.y; e0B[1]=d*d;
                d = xi0-xvB.z; e0B[2]=d*d;  d = xi0-xvB.w; e0B[3]=d*d;
                d = xi1-xvA.x; e1A[0]=d*d;  d = xi1-xvA.y; e1A[1]=d*d;
                d = xi1-xvA.z; e1A[2]=d*d;  d = xi1-xvA.w; e1A[3]=d*d;
                d = xi1-xvB.x; e1B[0]=d*d;  d = xi1-xvB.y; e1B[1]=d*d;
                d = xi1-xvB.z; e1B[2]=d*d;  d = xi1-xvB.w; e1B[3]=d*d;
            }

            #pragma unroll
            for (int m = 0; m < NMIX; m++) {
                float Bm = Bv[m];
                const int tb = (c*NMIX + m)*KB_JT;
                float4 cjA = *reinterpret_cast<const float4*>(&sC[tb + jA]);
                float4 sjA = *reinterpret_cast<const float4*>(&sS[tb + jA]);
                float4 cjB = *reinterpret_cast<const float4*>(&sC[tb + jB]);
                float4 sjB = *reinterpret_cast<const float4*>(&sS[tb + jB]);
                float cI0 = sFI[r0*30 + (c*NMIX + m)*2];
                float sI0 = sFI[r0*30 + (c*NMIX + m)*2 + 1];
                float cI1 = sFI[(r0+1)*30 + (c*NMIX + m)*2];
                float sI1 = sFI[(r0+1)*30 + (c*NMIX + m)*2 + 1];

                o0A[0*NCH+c] += ex2(Bm*e0A[0]) * (cI0*cjA.x + sI0*sjA.x);
                o0A[1*NCH+c] += ex2(Bm*e0A[1]) * (cI0*cjA.y + sI0*sjA.y);
                o0A[2*NCH+c] += ex2(Bm*e0A[2]) * (cI0*cjA.z + sI0*sjA.z);
                o0A[3*NCH+c] += ex2(Bm*e0A[3]) * (cI0*cjA.w + sI0*sjA.w);
                o0B[0*NCH+c] += ex2(Bm*e0B[0]) * (cI0*cjB.x + sI0*sjB.x);
                o0B[1*NCH+c] += ex2(Bm*e0B[1]) * (cI0*cjB.y + sI0*sjB.y);
                o0B[2*NCH+c] += ex2(Bm*e0B[2]) * (cI0*cjB.z + sI0*sjB.z);
                o0B[3*NCH+c] += ex2(Bm*e0B[3]) * (cI0*cjB.w + sI0*sjB.w);
                o1A[0*NCH+c] += ex2(Bm*e1A[0]) * (cI1*cjA.x + sI1*sjA.x);
                o1A[1*NCH+c] += ex2(Bm*e1A[1]) * (cI1*cjA.y + sI1*sjA.y);
                o1A[2*NCH+c] += ex2(Bm*e1A[2]) * (cI1*cjA.z + sI1*sjA.z);
                o1A[3*NCH+c] += ex2(Bm*e1A[3]) * (cI1*cjA.w + sI1*sjA.w);
                o1B[0*NCH+c] += ex2(Bm*e1B[0]) * (cI1*cjB.x + sI1*sjB.x);
                o1B[1*NCH+c] += ex2(Bm*e1B[1]) * (cI1*cjB.y + sI1*sjB.y);
                o1B[2*NCH+c] += ex2(Bm*e1B[2]) * (cI1*cjB.z + sI1*sjB.z);
                o1B[3*NCH+c] += ex2(Bm*e1B[3]) * (cI1*cjB.w + sI1*sjB.w);
            }
        }

        // diag + store (4 chunks: (row0|row1) x (A|B))
        #pragma unroll
        for (int rs = 0; rs < 4; rs++) {
            int   gi  = (rs < 2) ? gi0 : gi1;
            int   jl  = (rs & 1) ? jB : jA;
            float* o  = (rs == 0) ? o0A : (rs == 1) ? o0B : (rs == 2) ? o1A : o1B;
            int jj = gi - (jt0 + jl);
            if (jj >= 0 && jj < 4) {
                #pragma unroll
                for (int c = 0; c < NCH; c++) o[jj*NCH + c] += sd[c];
            }
            size_t base = ((size_t)(b*ND + gi)*ND + jt0 + jl) * NCH;
            float4* p = reinterpret_cast<float4*>(out + base);
            p[0] = make_float4(o[0], o[1], o[2],  o[3]);
            p[1] = make_float4(o[4], o[5], o[6],  o[7]);
            p[2] = make_float4(o[8], o[9], o[10], o[11]);
        }
    }
}

// ---------------------------------------------------------------------------
extern "C" void kernel_launch(void* const* d_in, const int* in_sizes, int n_in,
                              void* d_out, int out_size)
{
    const float* xc      = (const float*)d_in[0];
    const float* yc      = (const float*)d_in[1];
    const float* mu      = (const float*)d_in[2];
    const float* inv_std = (const float*)d_in[3];
    const float* likerr  = (const float*)d_in[4];
    const float* unif    = (const float*)d_in[5];
    const float* W1 = (const float*)d_in[6];  const float* b1 = (const float*)d_in[7];
    const float* W2 = (const float*)d_in[8];  const float* b2 = (const float*)d_in[9];
    const float* W3 = (const float*)d_in[10]; const float* b3 = (const float*)d_in[11];
    const float* W4 = (const float*)d_in[12]; const float* b4 = (const float*)d_in[13];
    const float* W5 = (const float*)d_in[14]; const float* b5 = (const float*)d_in[15];
    float* out = (float*)d_out;

    kA_feat <<< dim3(3, ND/64, NB*NCH), 256 >>>(xc, yc, mu, inv_std);
    k34_hmean_mlp <<< NB*NCH, 256 >>>(yc, W1, b1, W2, b2, W3, b3, W4, b4, W5, b5, unif);
    kB_out  <<< dim3(ND/KB_JT, ND/KB_IT, NB), 256 >>>(out, xc, mu, inv_std, likerr);
}

// round 11
// speedup vs baseline: 1.1146x; 1.1146x over previous
#include <cuda_runtime.h>
#include <math.h>

#define ND   768
#define NB   8
#define NCH  3
#define NMIX 5
#define NS   10
#define HH   10
#define PI2f 6.28318530717958647692f
#define ZITTERf 1e-4f
#define NPLANE (NB*NCH*NMIX)          // 120
#define LOG2Ef 1.4426950408889634f

__device__ float    g_feat[NPLANE * ND];   // zero-init; kA atomics; k34 reads then re-zeroes
__device__ float    g_hmean[NB * NCH * HH];
__device__ float    g_w[NB * NCH * NMIX];
__device__ unsigned g_ctr;                 // zero-init; k34 last-block counter (self-resetting)

__device__ __forceinline__ float ex2(float x) {
    float y; asm("ex2.approx.ftz.f32 %0, %1;" : "=f"(y) : "f"(x)); return y;
}

// ---------------------------------------------------------------------------
// Kernel A: feature[bc,m,i] = sum_j K_m(i,j)*yc[j], trig-separated.
// Tile: 64 i x 256 j. Thread: i = t>>2, jq = t&3 over 64 consecutive j.
// (unchanged — proven 22.2us)
// ---------------------------------------------------------------------------
#define JPA 280    // padded table stride for 256 j

__global__ void __launch_bounds__(256) kA_feat(const float* __restrict__ xc,
                                               const float* __restrict__ yc,
                                               const float* __restrict__ mu,
                                               const float* __restrict__ inv_std)
{
    int bc  = blockIdx.z;                 // b*3 + c
    int b   = bc / NCH, c = bc - b*NCH;
    int it  = blockIdx.y;
    int jt0 = blockIdx.x * 256;
    int t   = threadIdx.x;

    __shared__ float sC[NMIX*JPA], sS[NMIX*JPA], sXj[JPA];

    float Bv[NMIX], Pv[NMIX];
    #pragma unroll
    for (int m = 0; m < NMIX; m++) {
        float s = inv_std[m];
        Bv[m] = -0.5f * PI2f * PI2f * LOG2Ef * s * s;
        Pv[m] = PI2f * mu[m];
    }

    {   // table setup: every thread owns one j
        int j  = t;
        int gj = jt0 + j;
        float xjv = xc[(b*ND + gj)*NCH + c];
        float yjv = yc[(b*ND + gj)*NCH + c];
        int pj = j + ((j >> 6) << 3);
        sXj[pj] = xjv;
        #pragma unroll
        for (int m = 0; m < NMIX; m++) {
            float sn, cs;
            __sincosf(Pv[m] * xjv, &sn, &cs);
            sC[m*JPA + pj] = cs * yjv;
            sS[m*JPA + pj] = sn * yjv;
        }
    }
    __syncthreads();

    int i_loc = t >> 2, jq = t & 3;
    int gi = it*64 + i_loc;
    float xi = xc[(b*ND + gi)*NCH + c];

    float cI[NMIX], sI[NMIX];
    #pragma unroll
    for (int m = 0; m < NMIX; m++)
        __sincosf(Pv[m] * xi, &sI[m], &cI[m]);

    float accC[NMIX], accS[NMIX];
    #pragma unroll
    for (int m = 0; m < NMIX; m++) { accC[m] = 0.f; accS[m] = 0.f; }

    int gbase = jq * 72;
    #pragma unroll 4
    for (int ch = 0; ch < 16; ch++) {
        int off = gbase + ch*4;
        float4 xv = *reinterpret_cast<const float4*>(&sXj[off]);
        float d0 = xi - xv.x, d1 = xi - xv.y, d2 = xi - xv.z, d3 = xi - xv.w;
        float e0 = d0*d0, e1 = d1*d1, e2 = d2*d2, e3 = d3*d3;
        #pragma unroll
        for (int m = 0; m < NMIX; m++) {
            float Bm = Bv[m];
            float4 cj = *reinterpret_cast<const float4*>(&sC[m*JPA + off]);
            float4 sj = *reinterpret_cast<const float4*>(&sS[m*JPA + off]);
            float v0 = ex2(Bm*e0), v1 = ex2(Bm*e1), v2 = ex2(Bm*e2), v3 = ex2(Bm*e3);
            accC[m] += v0*cj.x + v1*cj.y + v2*cj.z + v3*cj.w;
            accS[m] += v0*sj.x + v1*sj.y + v2*sj.z + v3*sj.w;
        }
    }

    #pragma unroll
    for (int m = 0; m < NMIX; m++) {
        accC[m] += __shfl_xor_sync(0xffffffffu, accC[m], 1);
        accC[m] += __shfl_xor_sync(0xffffffffu, accC[m], 2);
        accS[m] += __shfl_xor_sync(0xffffffffu, accS[m], 1);
        accS[m] += __shfl_xor_sync(0xffffffffu, accS[m], 2);
    }
    if (jq == 0) {
        #pragma unroll
        for (int m = 0; m < NMIX; m++)
            atomicAdd(&g_feat[(bc*NMIX + m)*ND + gi],
                      cI[m]*accC[m] + sI[m]*accS[m]);
    }
}

// ---------------------------------------------------------------------------
// Kernel 34: per-bc hmean (+ re-zero g_feat), then last block runs the MLP
// + Gumbel-softmax. (unchanged)
// ---------------------------------------------------------------------------
__global__ void __launch_bounds__(256) k34_hmean_mlp(
        const float* __restrict__ yc,
        const float* __restrict__ W1, const float* __restrict__ b1,
        const float* __restrict__ W2, const float* __restrict__ b2,
        const float* __restrict__ W3, const float* __restrict__ b3,
        const float* __restrict__ W4, const float* __restrict__ b4,
        const float* __restrict__ W5, const float* __restrict__ b5,
        const float* __restrict__ unif)
{
    int bc = blockIdx.x;
    int b  = bc / NCH, c = bc - b*NCH;
    int t  = threadIdx.x;

    __shared__ float sW[HH*6], sb[HH], sh[HH];
    __shared__ float w2[300], w3[100], w4[100], w5[150];
    __shared__ float sb2[HH], sb3[HH], sb4[HH], sb5[15];
    __shared__ float su[NB*NS*NCH*NMIX];          // 1200 floats
    __shared__ float shm[NB][30], haL[NB][HH], hbL[NB][HH], ll[NB][15], swacc[NB][15];
    __shared__ bool  isLast;

    for (int u = t; u < 300; u += 256) w2[u] = W2[u];
    for (int u = t; u < 1200; u += 256) su[u] = unif[u];
    if (t < 100) { w3[t] = W3[t]; w4[t] = W4[t]; }
    if (t < 150) w5[t] = W5[t];
    if (t < HH)  { sb2[t] = b2[t]; sb3[t] = b3[t]; sb4[t] = b4[t]; }
    if (t < 15)  sb5[t] = b5[t];
    if (t < HH*6) sW[t] = W1[t];
    if (t < HH)  { sb[t] = b1[t]; sh[t] = 0.f; }
    __syncthreads();

    float hacc[HH];
    #pragma unroll
    for (int k = 0; k < HH; k++) hacc[k] = 0.f;

    for (int i = t; i < ND; i += 256) {
        float ycv = yc[(b*ND + i)*NCH + c];
        float f[6];
        #pragma unroll
        for (int m = 0; m < NMIX; m++) {
            int idx = (bc*NMIX + m)*ND + i;
            f[m] = g_feat[idx] + ZITTERf * ycv;
            g_feat[idx] = 0.f;                    // restore invariant for next replay
        }
        f[5] = ycv;
        #pragma unroll
        for (int k = 0; k < HH; k++) {
            float s = sb[k];
            #pragma unroll
            for (int u = 0; u < 6; u++) s += sW[k*6 + u] * f[u];
            hacc[k] += fmaxf(s, 0.f);
        }
    }
    #pragma unroll
    for (int k = 0; k < HH; k++) atomicAdd(&sh[k], hacc[k]);
    __syncthreads();
    if (t < HH)
        g_hmean[b*(NCH*HH) + c*HH + t] = sh[t] * (1.0f/ND);

    __threadfence();
    __syncthreads();
    if (t == 0) isLast = (atomicAdd(&g_ctr, 1u) == (unsigned)(NB*NCH - 1));
    __syncthreads();
    if (!isLast) return;
    if (t == 0) g_ctr = 0;

    if (t < NB*30) {
        const volatile float* hmv = g_hmean;
        shm[t/30][t%30] = hmv[t];
    }
    if (t < NB*15) swacc[t/15][t%15] = 0.f;
    __syncthreads();

    if (t < NB*HH) {
        int bb = t/HH, k = t%HH;
        float s = sb2[k];
        #pragma unroll
        for (int u = 0; u < 30; u++) s += w2[k*30+u] * shm[bb][u];
        haL[bb][k] = fmaxf(s, 0.f);
    }
    __syncthreads();
    if (t < NB*HH) {
        int bb = t/HH, k = t%HH;
        float s = sb3[k];
        #pragma unroll
        for (int u = 0; u < HH; u++) s += w3[k*HH+u] * haL[bb][u];
        hbL[bb][k] = fmaxf(s, 0.f);
    }
    __syncthreads();
    if (t < NB*HH) {
        int bb = t/HH, k = t%HH;
        float s = sb4[k];
        #pragma unroll
        for (int u = 0; u < HH; u++) s += w4[k*HH+u] * hbL[bb][u];
        haL[bb][k] = fmaxf(s, 0.f);
    }
    __syncthreads();
    if (t < NB*15) {
        int bb = t/15, n = t%15;
        float s = sb5[n];
        #pragma unroll
        for (int k = 0; k < HH; k++) s += w5[n*HH+k] * haL[bb][k];
        ll[bb][n] = s;
    }
    __syncthreads();

    if (t < NB*NS*NCH) {
        int bb = t / (NS*NCH);
        int rem = t % (NS*NCH);
        int s_ = rem / NCH, cc = rem % NCH;
        float z[NMIX], mx = -1e30f;
        #pragma unroll
        for (int m = 0; m < NMIX; m++) {
            float u = su[((bb*NS + s_)*NCH + cc)*NMIX + m];
            float g = -__logf(-__logf(u + 1e-20f));
            z[m] = (g + ll[bb][cc*NMIX + m]) * 10.0f;   // 1/TEMP
            mx = fmaxf(mx, z[m]);
        }
        float sum = 0.f;
        #pragma unroll
        for (int m = 0; m < NMIX; m++) { z[m] = __expf(z[m] - mx); sum += z[m]; }
        float inv = 1.0f / (sum * (float)NS);
        #pragma unroll
        for (int m = 0; m < NMIX; m++)
            atomicAdd(&swacc[bb][cc*NMIX + m], z[m] * inv);
    }
    __syncthreads();
    if (t < NB*NCH*NMIX)
        g_w[t] = swacc[t/(NCH*NMIX)][t%(NCH*NMIX)];
}

// ---------------------------------------------------------------------------
// Kernel B (v4): out[b,i,j,c] = sum_m w*K + diag. Trig-separated, full grid.
// Tile 32 i x 64 j; block 256 = 16 tx (j-quads) x 16 ty (2 rows each).
// KEY: thread's 4 j's are FIXED, so each (c,m) table float4 pair is loaded
// ONCE and reused for both rows -> 30 LDS.128/thread (vs ~120 before).
// Accumulators only 2 rows x 12 = 24 regs -> no spill (~80 regs total).
// Stores: R4's proven contiguous 16-lane x 48B geometry.
// ---------------------------------------------------------------------------
#define KB_IT 32
#define KB_JT 64

__global__ void __launch_bounds__(256) kB_out(float* __restrict__ out,
                                              const float* __restrict__ xc,
                                              const float* __restrict__ mu,
                                              const float* __restrict__ inv_std,
                                              const float* __restrict__ likerr)
{
    int b   = blockIdx.z;
    int it0 = blockIdx.y * KB_IT;
    int jt0 = blockIdx.x * KB_JT;
    int t   = threadIdx.x;

    __shared__ float sC[NCH*NMIX*KB_JT];   // (cos(P*xj) * w)  [c*5+m][j], contiguous 64
    __shared__ float sS[NCH*NMIX*KB_JT];   // (sin(P*xj) * w)
    __shared__ float sXj[NCH*KB_JT];
    __shared__ float sXi[NCH*KB_IT];
    __shared__ float sFI[KB_IT*30];        // [row][(c*5+m)*2 + {cos,sin}]

    float Bv[NMIX], Pv[NMIX];
    #pragma unroll
    for (int m = 0; m < NMIX; m++) {
        float s = inv_std[m];
        Bv[m] = -0.5f * PI2f * PI2f * LOG2Ef * s * s;
        Pv[m] = PI2f * mu[m];
    }
    float sd[NCH];
    #pragma unroll
    for (int c = 0; c < NCH; c++) {
        float l = fminf(fmaxf(likerr[c], 0.1f), 1.0f);
        sd[c] = ZITTERf + l*l;
    }

    if (t < KB_JT) {                       // j tables
        int j = t;
        #pragma unroll
        for (int c = 0; c < NCH; c++) {
            float xjv = xc[(b*ND + jt0 + j)*NCH + c];
            sXj[c*KB_JT + j] = xjv;
            #pragma unroll
            for (int m = 0; m < NMIX; m++) {
                float sn, cs;
                __sincosf(Pv[m] * xjv, &sn, &cs);
                float wv = g_w[(b*NCH + c)*NMIX + m];
                sC[(c*NMIX + m)*KB_JT + j] = cs * wv;
                sS[(c*NMIX + m)*KB_JT + j] = sn * wv;
            }
        }
    }
    for (int u = t; u < KB_IT*15; u += 256) {   // i tables
        int row = u / 15, cm = u % 15, c = cm / 5, m = cm % 5;
        float xiv = xc[(b*ND + it0 + row)*NCH + c];
        float sn, cs;
        __sincosf(Pv[m] * xiv, &sn, &cs);
        sFI[row*30 + cm*2    ] = cs;
        sFI[row*30 + cm*2 + 1] = sn;
        if (m == 0) sXi[c*KB_IT + row] = xiv;
    }
    __syncthreads();

    int tx = t & 15, ty = t >> 4;
    int j0 = tx * 4;
    int r0 = ty * 2;                       // rows r0, r0+1
    int gi0 = it0 + r0, gi1 = gi0 + 1;

    float xj[NCH][4];
    #pragma unroll
    for (int c = 0; c < NCH; c++) {
        float4 xv = *reinterpret_cast<const float4*>(&sXj[c*KB_JT + j0]);
        xj[c][0] = xv.x; xj[c][1] = xv.y; xj[c][2] = xv.z; xj[c][3] = xv.w;
    }

    float o0[12], o1[12];
    #pragma unroll
    for (int u = 0; u < 12; u++) { o0[u] = 0.f; o1[u] = 0.f; }

    #pragma unroll
    for (int c = 0; c < NCH; c++) {
        float xi0 = sXi[c*KB_IT + r0];
        float xi1 = sXi[c*KB_IT + r0 + 1];
        float e0[4], e1[4];
        #pragma unroll
        for (int q = 0; q < 4; q++) {
            float d0 = xi0 - xj[c][q]; e0[q] = d0*d0;
            float d1 = xi1 - xj[c][q]; e1[q] = d1*d1;
        }
        #pragma unroll
        for (int m = 0; m < NMIX; m++) {
            float Bm = Bv[m];
            const int tb = (c*NMIX + m)*KB_JT + j0;
            float4 cj = *reinterpret_cast<const float4*>(&sC[tb]);
            float4 sj = *reinterpret_cast<const float4*>(&sS[tb]);
            int fo = (c*NMIX + m)*2;
            float cI0 = sFI[r0*30 + fo],       sI0 = sFI[r0*30 + fo + 1];
            float cI1 = sFI[(r0+1)*30 + fo],   sI1 = sFI[(r0+1)*30 + fo + 1];

            o0[0*NCH+c] += ex2(Bm*e0[0]) * (cI0*cj.x + sI0*sj.x);
            o0[1*NCH+c] += ex2(Bm*e0[1]) * (cI0*cj.y + sI0*sj.y);
            o0[2*NCH+c] += ex2(Bm*e0[2]) * (cI0*cj.z + sI0*sj.z);
            o0[3*NCH+c] += ex2(Bm*e0[3]) * (cI0*cj.w + sI0*sj.w);
            o1[0*NCH+c] += ex2(Bm*e1[0]) * (cI1*cj.x + sI1*sj.x);
            o1[1*NCH+c] += ex2(Bm*e1[1]) * (cI1*cj.y + sI1*sj.y);
            o1[2*NCH+c] += ex2(Bm*e1[2]) * (cI1*cj.z + sI1*sj.z);
            o1[3*NCH+c] += ex2(Bm*e1[3]) * (cI1*cj.w + sI1*sj.w);
        }
    }

    // diagonal noise
    {
        int jj0 = gi0 - (jt0 + j0);
        if (jj0 >= 0 && jj0 < 4) {
            #pragma unroll
            for (int c = 0; c < NCH; c++) o0[jj0*NCH + c] += sd[c];
        }
        int jj1 = gi1 - (jt0 + j0);
        if (jj1 >= 0 && jj1 < 4) {
            #pragma unroll
            for (int c = 0; c < NCH; c++) o1[jj1*NCH + c] += sd[c];
        }
    }

    // stores: contiguous 48B per lane, 16 lanes per row = 768B runs
    {
        size_t base0 = ((size_t)(b*ND + gi0)*ND + jt0 + j0) * NCH;
        float4* p0 = reinterpret_cast<float4*>(out + base0);
        p0[0] = make_float4(o0[0], o0[1], o0[2],  o0[3]);
        p0[1] = make_float4(o0[4], o0[5], o0[6],  o0[7]);
        p0[2] = make_float4(o0[8], o0[9], o0[10], o0[11]);
        size_t base1 = ((size_t)(b*ND + gi1)*ND + jt0 + j0) * NCH;
        float4* p1 = reinterpret_cast<float4*>(out + base1);
        p1[0] = make_float4(o1[0], o1[1], o1[2],  o1[3]);
        p1[1] = make_float4(o1[4], o1[5], o1[6],  o1[7]);
        p1[2] = make_float4(o1[8], o1[9], o1[10], o1[11]);
    }
}

// ---------------------------------------------------------------------------
extern "C" void kernel_launch(void* const* d_in, const int* in_sizes, int n_in,
                              void* d_out, int out_size)
{
    const float* xc      = (const float*)d_in[0];
    const float* yc      = (const float*)d_in[1];
    const float* mu      = (const float*)d_in[2];
    const float* inv_std = (const float*)d_in[3];
    const float* likerr  = (const float*)d_in[4];
    const float* unif    = (const float*)d_in[5];
    const float* W1 = (const float*)d_in[6];  const float* b1 = (const float*)d_in[7];
    const float* W2 = (const float*)d_in[8];  const float* b2 = (const float*)d_in[9];
    const float* W3 = (const float*)d_in[10]; const float* b3 = (const float*)d_in[11];
    const float* W4 = (const float*)d_in[12]; const float* b4 = (const float*)d_in[13];
    const float* W5 = (const float*)d_in[14]; const float* b5 = (const float*)d_in[15];
    float* out = (float*)d_out;

    kA_feat <<< dim3(3, ND/64, NB*NCH), 256 >>>(xc, yc, mu, inv_std);
    k34_hmean_mlp <<< NB*NCH, 256 >>>(yc, W1, b1, W2, b2, W3, b3, W4, b4, W5, b5, unif);
    kB_out  <<< dim3(ND/KB_JT, ND/KB_IT, NB), 256 >>>(out, xc, mu, inv_std, likerr);
}

// round 12
// speedup vs baseline: 1.2047x; 1.0808x over previous
#include <cuda_runtime.h>
#include <math.h>

#define ND   768
#define NB   8
#define NCH  3
#define NMIX 5
#define NS   10
#define HH   10
#define PI2f 6.28318530717958647692f
#define ZITTERf 1e-4f
#define NPLANE (NB*NCH*NMIX)          // 120
#define LOG2Ef 1.4426950408889634f

__device__ float    g_feat[NPLANE * ND];   // zero-init; kA atomics; k34 reads then re-zeroes
__device__ float    g_hmean[NB * NCH * HH];
__device__ float    g_w[NB * NCH * NMIX];
__device__ unsigned g_ctr;                 // zero-init; k34 last-block counter (self-resetting)

__device__ __forceinline__ float ex2(float x) {
    float y; asm("ex2.approx.ftz.f32 %0, %1;" : "=f"(y) : "f"(x)); return y;
}

// ---------------------------------------------------------------------------
// Dummy kernel: shifts the ncu capture window (-s 5 -c 1) so launch #6 = kB.
// ---------------------------------------------------------------------------
__global__ void kDummy() {}

// ---------------------------------------------------------------------------
// Kernel A: feature[bc,m,i] = sum_j K_m(i,j)*yc[j], trig-separated.
// Tile: 64 i x 256 j. Thread: i = t>>2, jq = t&3 over 64 consecutive j.
// (proven 22.2us)
// ---------------------------------------------------------------------------
#define JPA 280    // padded table stride for 256 j

__global__ void __launch_bounds__(256) kA_feat(const float* __restrict__ xc,
                                               const float* __restrict__ yc,
                                               const float* __restrict__ mu,
                                               const float* __restrict__ inv_std)
{
    int bc  = blockIdx.z;                 // b*3 + c
    int b   = bc / NCH, c = bc - b*NCH;
    int it  = blockIdx.y;
    int jt0 = blockIdx.x * 256;
    int t   = threadIdx.x;

    __shared__ float sC[NMIX*JPA], sS[NMIX*JPA], sXj[JPA];

    float Bv[NMIX], Pv[NMIX];
    #pragma unroll
    for (int m = 0; m < NMIX; m++) {
        float s = inv_std[m];
        Bv[m] = -0.5f * PI2f * PI2f * LOG2Ef * s * s;
        Pv[m] = PI2f * mu[m];
    }

    {   // table setup: every thread owns one j
        int j  = t;
        int gj = jt0 + j;
        float xjv = xc[(b*ND + gj)*NCH + c];
        float yjv = yc[(b*ND + gj)*NCH + c];
        int pj = j + ((j >> 6) << 3);
        sXj[pj] = xjv;
        #pragma unroll
        for (int m = 0; m < NMIX; m++) {
            float sn, cs;
            __sincosf(Pv[m] * xjv, &sn, &cs);
            sC[m*JPA + pj] = cs * yjv;
            sS[m*JPA + pj] = sn * yjv;
        }
    }
    __syncthreads();

    int i_loc = t >> 2, jq = t & 3;
    int gi = it*64 + i_loc;
    float xi = xc[(b*ND + gi)*NCH + c];

    float cI[NMIX], sI[NMIX];
    #pragma unroll
    for (int m = 0; m < NMIX; m++)
        __sincosf(Pv[m] * xi, &sI[m], &cI[m]);

    float accC[NMIX], accS[NMIX];
    #pragma unroll
    for (int m = 0; m < NMIX; m++) { accC[m] = 0.f; accS[m] = 0.f; }

    int gbase = jq * 72;
    #pragma unroll 4
    for (int ch = 0; ch < 16; ch++) {
        int off = gbase + ch*4;
        float4 xv = *reinterpret_cast<const float4*>(&sXj[off]);
        float d0 = xi - xv.x, d1 = xi - xv.y, d2 = xi - xv.z, d3 = xi - xv.w;
        float e0 = d0*d0, e1 = d1*d1, e2 = d2*d2, e3 = d3*d3;
        #pragma unroll
        for (int m = 0; m < NMIX; m++) {
            float Bm = Bv[m];
            float4 cj = *reinterpret_cast<const float4*>(&sC[m*JPA + off]);
            float4 sj = *reinterpret_cast<const float4*>(&sS[m*JPA + off]);
            float v0 = ex2(Bm*e0), v1 = ex2(Bm*e1), v2 = ex2(Bm*e2), v3 = ex2(Bm*e3);
            accC[m] += v0*cj.x + v1*cj.y + v2*cj.z + v3*cj.w;
            accS[m] += v0*sj.x + v1*sj.y + v2*sj.z + v3*sj.w;
        }
    }

    #pragma unroll
    for (int m = 0; m < NMIX; m++) {
        accC[m] += __shfl_xor_sync(0xffffffffu, accC[m], 1);
        accC[m] += __shfl_xor_sync(0xffffffffu, accC[m], 2);
        accS[m] += __shfl_xor_sync(0xffffffffu, accS[m], 1);
        accS[m] += __shfl_xor_sync(0xffffffffu, accS[m], 2);
    }
    if (jq == 0) {
        #pragma unroll
        for (int m = 0; m < NMIX; m++)
            atomicAdd(&g_feat[(bc*NMIX + m)*ND + gi],
                      cI[m]*accC[m] + sI[m]*accS[m]);
    }
}

// ---------------------------------------------------------------------------
// Kernel 34: per-bc hmean (+ re-zero g_feat), then last block runs the MLP
// + Gumbel-softmax. (unchanged)
// ---------------------------------------------------------------------------
__global__ void __launch_bounds__(256) k34_hmean_mlp(
        const float* __restrict__ yc,
        const float* __restrict__ W1, const float* __restrict__ b1,
        const float* __restrict__ W2, const float* __restrict__ b2,
        const float* __restrict__ W3, const float* __restrict__ b3,
        const float* __restrict__ W4, const float* __restrict__ b4,
        const float* __restrict__ W5, const float* __restrict__ b5,
        const float* __restrict__ unif)
{
    int bc = blockIdx.x;
    int b  = bc / NCH, c = bc - b*NCH;
    int t  = threadIdx.x;

    __shared__ float sW[HH*6], sb[HH], sh[HH];
    __shared__ float w2[300], w3[100], w4[100], w5[150];
    __shared__ float sb2[HH], sb3[HH], sb4[HH], sb5[15];
    __shared__ float su[NB*NS*NCH*NMIX];          // 1200 floats
    __shared__ float shm[NB][30], haL[NB][HH], hbL[NB][HH], ll[NB][15], swacc[NB][15];
    __shared__ bool  isLast;

    for (int u = t; u < 300; u += 256) w2[u] = W2[u];
    for (int u = t; u < 1200; u += 256) su[u] = unif[u];
    if (t < 100) { w3[t] = W3[t]; w4[t] = W4[t]; }
    if (t < 150) w5[t] = W5[t];
    if (t < HH)  { sb2[t] = b2[t]; sb3[t] = b3[t]; sb4[t] = b4[t]; }
    if (t < 15)  sb5[t] = b5[t];
    if (t < HH*6) sW[t] = W1[t];
    if (t < HH)  { sb[t] = b1[t]; sh[t] = 0.f; }
    __syncthreads();

    float hacc[HH];
    #pragma unroll
    for (int k = 0; k < HH; k++) hacc[k] = 0.f;

    for (int i = t; i < ND; i += 256) {
        float ycv = yc[(b*ND + i)*NCH + c];
        float f[6];
        #pragma unroll
        for (int m = 0; m < NMIX; m++) {
            int idx = (bc*NMIX + m)*ND + i;
            f[m] = g_feat[idx] + ZITTERf * ycv;
            g_feat[idx] = 0.f;                    // restore invariant for next replay
        }
        f[5] = ycv;
        #pragma unroll
        for (int k = 0; k < HH; k++) {
            float s = sb[k];
            #pragma unroll
            for (int u = 0; u < 6; u++) s += sW[k*6 + u] * f[u];
            hacc[k] += fmaxf(s, 0.f);
        }
    }
    #pragma unroll
    for (int k = 0; k < HH; k++) atomicAdd(&sh[k], hacc[k]);
    __syncthreads();
    if (t < HH)
        g_hmean[b*(NCH*HH) + c*HH + t] = sh[t] * (1.0f/ND);

    __threadfence();
    __syncthreads();
    if (t == 0) isLast = (atomicAdd(&g_ctr, 1u) == (unsigned)(NB*NCH - 1));
    __syncthreads();
    if (!isLast) return;
    if (t == 0) g_ctr = 0;

    if (t < NB*30) {
        const volatile float* hmv = g_hmean;
        shm[t/30][t%30] = hmv[t];
    }
    if (t < NB*15) swacc[t/15][t%15] = 0.f;
    __syncthreads();

    if (t < NB*HH) {
        int bb = t/HH, k = t%HH;
        float s = sb2[k];
        #pragma unroll
        for (int u = 0; u < 30; u++) s += w2[k*30+u] * shm[bb][u];
        haL[bb][k] = fmaxf(s, 0.f);
    }
    __syncthreads();
    if (t < NB*HH) {
        int bb = t/HH, k = t%HH;
        float s = sb3[k];
        #pragma unroll
        for (int u = 0; u < HH; u++) s += w3[k*HH+u] * haL[bb][u];
        hbL[bb][k] = fmaxf(s, 0.f);
    }
    __syncthreads();
    if (t < NB*HH) {
        int bb = t/HH, k = t%HH;
        float s = sb4[k];
        #pragma unroll
        for (int u = 0; u < HH; u++) s += w4[k*HH+u] * hbL[bb][u];
        haL[bb][k] = fmaxf(s, 0.f);
    }
    __syncthreads();
    if (t < NB*15) {
        int bb = t/15, n = t%15;
        float s = sb5[n];
        #pragma unroll
        for (int k = 0; k < HH; k++) s += w5[n*HH+k] * haL[bb][k];
        ll[bb][n] = s;
    }
    __syncthreads();

    if (t < NB*NS*NCH) {
        int bb = t / (NS*NCH);
        int rem = t % (NS*NCH);
        int s_ = rem / NCH, cc = rem % NCH;
        float z[NMIX], mx = -1e30f;
        #pragma unroll
        for (int m = 0; m < NMIX; m++) {
            float u = su[((bb*NS + s_)*NCH + cc)*NMIX + m];
            float g = -__logf(-__logf(u + 1e-20f));
            z[m] = (g + ll[bb][cc*NMIX + m]) * 10.0f;   // 1/TEMP
            mx = fmaxf(mx, z[m]);
        }
        float sum = 0.f;
        #pragma unroll
        for (int m = 0; m < NMIX; m++) { z[m] = __expf(z[m] - mx); sum += z[m]; }
        float inv = 1.0f / (sum * (float)NS);
        #pragma unroll
        for (int m = 0; m < NMIX; m++)
            atomicAdd(&swacc[bb][cc*NMIX + m], z[m] * inv);
    }
    __syncthreads();
    if (t < NB*NCH*NMIX)
        g_w[t] = swacc[t/(NCH*NMIX)][t%(NCH*NMIX)];
}

// ---------------------------------------------------------------------------
// Kernel B (R7 version, best known): symmetric upper-triangle, trig-separated,
// mirror tile staged in dynamic smem, w folded into j tables.
// ---------------------------------------------------------------------------
#define KB_JPAD 88
#define KB_MSTR 196
#define KB_SM_F   (64*KB_MSTR)                 // 12544 mirror floats
#define KB_C_OFF  KB_SM_F
#define KB_S_OFF  (KB_C_OFF + NCH*NMIX*KB_JPAD)
#define KB_XJ_OFF (KB_S_OFF + NCH*NMIX*KB_JPAD)
#define KB_TOT_F  (KB_XJ_OFF + NCH*KB_JPAD)
#define KB_TOT_B  (KB_TOT_F * 4)

__global__ void __launch_bounds__(256) kB_out(float* __restrict__ out,
                                              const float* __restrict__ xc,
                                              const float* __restrict__ mu,
                                              const float* __restrict__ inv_std,
                                              const float* __restrict__ likerr)
{
    int b  = blockIdx.z;
    int tI = blockIdx.y, tJ = blockIdx.x;
    if (tJ < tI) return;
    bool offdiag = (tI != tJ);

    extern __shared__ float smem[];
    float* sM  = smem;
    float* sC  = smem + KB_C_OFF;
    float* sS  = smem + KB_S_OFF;
    float* sXj = smem + KB_XJ_OFF;

    int t = threadIdx.x;

    float Bv[NMIX], Pv[NMIX];
    #pragma unroll
    for (int m = 0; m < NMIX; m++) {
        float s = inv_std[m];
        Bv[m] = -0.5f * PI2f * PI2f * LOG2Ef * s * s;
        Pv[m] = PI2f * mu[m];
    }
    float sd[NCH];
    #pragma unroll
    for (int c = 0; c < NCH; c++) {
        float l = fminf(fmaxf(likerr[c], 0.1f), 1.0f);
        sd[c] = ZITTERf + l*l;
    }

    if (t < 64) {
        int pj = t + ((t >> 4) << 3);
        #pragma unroll
        for (int c = 0; c < NCH; c++) {
            float xjv = xc[(b*ND + tJ*64 + t)*NCH + c];
            sXj[c*KB_JPAD + pj] = xjv;
            #pragma unroll
            for (int m = 0; m < NMIX; m++) {
                float sn, cs;
                __sincosf(Pv[m] * xjv, &sn, &cs);
                float wv = g_w[(b*NCH + c)*NMIX + m];
                sC[(c*NMIX + m)*KB_JPAD + pj] = cs * wv;
                sS[(c*NMIX + m)*KB_JPAD + pj] = sn * wv;
            }
        }
    }
    __syncthreads();

    int i_loc = t >> 2, jq = t & 3;
    int gi = tI*64 + i_loc;

    float xi[NCH], cI[NCH][NMIX], sI[NCH][NMIX];
    #pragma unroll
    for (int c = 0; c < NCH; c++) {
        xi[c] = xc[(b*ND + gi)*NCH + c];
        #pragma unroll
        for (int m = 0; m < NMIX; m++)
            __sincosf(Pv[m] * xi[c], &sI[c][m], &cI[c][m]);
    }

    bool diagT = (!offdiag) && ((i_loc >> 4) == jq);
    int  dq = (i_loc & 15) >> 2, dk = i_loc & 3;

    #pragma unroll
    for (int q = 0; q < 4; q++) {
        int slot = jq*24 + q*4;
        float a12[12];
        #pragma unroll
        for (int c = 0; c < NCH; c++) {
            float4 xv = *reinterpret_cast<const float4*>(&sXj[c*KB_JPAD + slot]);
            float d0 = xi[c] - xv.x, d1 = xi[c] - xv.y,
                  d2 = xi[c] - xv.z, d3 = xi[c] - xv.w;
            float e0 = d0*d0, e1 = d1*d1, e2 = d2*d2, e3 = d3*d3;
            float acc0 = 0.f, acc1 = 0.f, acc2 = 0.f, acc3 = 0.f;
            #pragma unroll
            for (int m = 0; m < NMIX; m++) {
                float Bm = Bv[m], cIm = cI[c][m], sIm = sI[c][m];
                float4 cj = *reinterpret_cast<const float4*>(&sC[(c*NMIX + m)*KB_JPAD + slot]);
                float4 sj = *reinterpret_cast<const float4*>(&sS[(c*NMIX + m)*KB_JPAD + slot]);
                acc0 += ex2(Bm*e0) * (cIm*cj.x + sIm*sj.x);
                acc1 += ex2(Bm*e1) * (cIm*cj.y + sIm*sj.y);
                acc2 += ex2(Bm*e2) * (cIm*cj.z + sIm*sj.z);
                acc3 += ex2(Bm*e3) * (cIm*cj.w + sIm*sj.w);
            }
            a12[0*NCH + c] = acc0; a12[1*NCH + c] = acc1;
            a12[2*NCH + c] = acc2; a12[3*NCH + c] = acc3;
        }

        if (diagT && dq == q) {
            #pragma unroll
            for (int c = 0; c < NCH; c++) a12[dk*NCH + c] += sd[c];
        }

        size_t base = ((size_t)(b*ND + gi)*ND + tJ*64 + jq*16 + q*4) * NCH;
        float4* p = reinterpret_cast<float4*>(out + base);
        p[0] = make_float4(a12[0], a12[1], a12[2],  a12[3]);
        p[1] = make_float4(a12[4], a12[5], a12[6],  a12[7]);
        p[2] = make_float4(a12[8], a12[9], a12[10], a12[11]);

        if (offdiag) {
            #pragma unroll
            for (int jj = 0; jj < 4; jj++) {
                int jr = jq*16 + q*4 + jj;
                #pragma unroll
                for (int c = 0; c < NCH; c++)
                    sM[jr*KB_MSTR + i_loc*NCH + c] = a12[jj*NCH + c];
            }
        }
    }

    if (offdiag) {
        __syncthreads();
        #pragma unroll 4
        for (int f = t; f < 64*48; f += 256) {
            int r  = f / 48;
            int c4 = f - r*48;
            int s0 = r*KB_MSTR + c4*4;
            float4 v = *reinterpret_cast<const float4*>(&sM[s0]);
            reinterpret_cast<float4*>(
                out + ((size_t)(b*ND + tJ*64 + r)*ND + tI*64) * NCH)[c4] = v;
        }
    }
}

// ---------------------------------------------------------------------------
extern "C" void kernel_launch(void* const* d_in, const int* in_sizes, int n_in,
                              void* d_out, int out_size)
{
    const float* xc      = (const float*)d_in[0];
    const float* yc      = (const float*)d_in[1];
    const float* mu      = (const float*)d_in[2];
    const float* inv_std = (const float*)d_in[3];
    const float* likerr  = (const float*)d_in[4];
    const float* unif    = (const float*)d_in[5];
    const float* W1 = (const float*)d_in[6];  const float* b1 = (const float*)d_in[7];
    const float* W2 = (const float*)d_in[8];  const float* b2 = (const float*)d_in[9];
    const float* W3 = (const float*)d_in[10]; const float* b3 = (const float*)d_in[11];
    const float* W4 = (const float*)d_in[12]; const float* b4 = (const float*)d_in[13];
    const float* W5 = (const float*)d_in[14]; const float* b5 = (const float*)d_in[15];
    float* out = (float*)d_out;

    cudaFuncSetAttribute(kB_out, cudaFuncAttributeMaxDynamicSharedMemorySize, KB_TOT_B);

    kDummy  <<< 1, 1 >>>();   // shifts ncu capture window so launch #6 lands on kB_out
    kA_feat <<< dim3(3, ND/64, NB*NCH), 256 >>>(xc, yc, mu, inv_std);
    k34_hmean_mlp <<< NB*NCH, 256 >>>(yc, W1, b1, W2, b2, W3, b3, W4, b4, W5, b5, unif);
    kB_out  <<< dim3(ND/64, ND/64, NB), 256, KB_TOT_B >>>(out, xc, mu, inv_std, likerr);
}